// round 8
// baseline (speedup 1.0000x reference)
#include <cuda_runtime.h>
#include <cstdint>

// ConvSepKanCell: per-pixel dynamic KAN — float2, 2 outputs/thread,
// cp.async double-buffered smem pipeline for the coef stream.
// x: (2, 16, 128, 128) f32   w: (2, 3328, 128, 128) f32   out: (2, 16, 128, 128) f32
// Param layout along dim-1 of w (per pixel):
//   [0, 2816)      coef[i][o][m]  (16 x 16 x 11)   plane = i*176 + o*11 + m
//   [2816, 3072)   uw[i][o]
//   [3072, 3328)   rw[i][o]
// y[o] = sum_i uw[i][o] * (sum_m coef[i][o][m]*B3_m(x_i)) + rw[i][o]*silu(x_i)

#define HW      16384
#define HW2     8192
#define PLANE_B 65536ull          // bytes per parameter plane
#define INC     16
#define OUTC    16
#define COEFM   11
#define SIZE_W  3328
#define I0      2816
#define I1      3072
#define OSPLIT  8                 // 2 outputs per thread
#define TPB     128
#define NW      4                 // warps per CTA
#define PLANES  22                // coef planes pipelined per iteration (2 outputs x 11)
#define SEG_B   256               // bytes per (plane, warp) segment
#define STAGE_B (PLANES * NW * SEG_B)   // 22528

__device__ __forceinline__ float2 ldcs2(const float2* p) { return __ldcs(p); }

__device__ __forceinline__ void cp16(uint32_t dst, const void* src) {
    asm volatile("cp.async.cg.shared.global [%0], [%1], 16;" :: "r"(dst), "l"(src) : "memory");
}
__device__ __forceinline__ void cp_commit() {
    asm volatile("cp.async.commit_group;" ::: "memory");
}
template <int N>
__device__ __forceinline__ void cp_wait() {
    asm volatile("cp.async.wait_group %0;" :: "n"(N) : "memory");
}

__global__ __launch_bounds__(TPB, 5)
void kan_kernel(const float* __restrict__ x,
                const float* __restrict__ w,
                float* __restrict__ out)
{
    __shared__ __align__(16) char sbuf[2 * STAGE_B];   // 44 KB

    const int t     = blockIdx.x * TPB + threadIdx.x;   // float2 slot
    const int slice = blockIdx.y;                       // 0..7
    const int b    = t >> 13;
    const int hw2  = t & (HW2 - 1);
    const int warp = threadIdx.x >> 5;
    const int lane = threadIdx.x & 31;

    const char* wbase = (const char*)w + (size_t)b * SIZE_W * PLANE_B;
    const size_t row_byte = (size_t)(hw2 & ~31) * 8;     // warp-aligned byte in plane

    const float2* wp = (const float2*)(w + (size_t)b * SIZE_W * HW) + hw2;
    const float2* xp = (const float2*)(x + (size_t)b * INC * HW) + hw2;
    const float2* up = wp + (size_t)(I0 + slice * 2) * HW2;
    const float2* rp = wp + (size_t)(I1 + slice * 2) * HW2;

    const uint32_t sb = (uint32_t)__cvta_generic_to_shared(sbuf);
    // this thread's cp.async slot: plane p = 2k + (lane>>4), byte (lane&15)*16
    const int pf_po   = lane >> 4;          // plane parity
    const int pf_byte = (lane & 15) * 16;

    // prologue: issue coef loads for i = 0 into stage 0
    {
        const char* src0 = wbase + (size_t)(slice * PLANES) * PLANE_B + row_byte;
        #pragma unroll
        for (int k = 0; k < 11; ++k) {
            const int p = 2 * k + pf_po;
            const uint32_t dst = sb + (uint32_t)((p * NW + warp) * SEG_B + pf_byte);
            cp16(dst, src0 + (size_t)p * PLANE_B + pf_byte);
        }
        cp_commit();
    }

    float y0a = 0.f, y0b = 0.f, y1a = 0.f, y1b = 0.f;

    for (int i = 0; i < INC; ++i) {
        const int st = i & 1;

        if (i < INC - 1) {
            // issue coef loads for i+1 into the other stage
            const char* srcn = wbase + (size_t)((i + 1) * OUTC * COEFM + slice * PLANES) * PLANE_B + row_byte;
            const uint32_t stbase = sb + (uint32_t)((st ^ 1) * STAGE_B);
            #pragma unroll
            for (int k = 0; k < 11; ++k) {
                const int p = 2 * k + pf_po;
                const uint32_t dst = stbase + (uint32_t)((p * NW + warp) * SEG_B + pf_byte);
                cp16(dst, srcn + (size_t)p * PLANE_B + pf_byte);
            }
            cp_commit();
            cp_wait<1>();          // stage for i is complete
        } else {
            cp_wait<0>();
        }
        __syncwarp();              // publish other lanes' cp.async data

        const float2 xi = __ldg(xp);
        xp += HW2;

        // ---- Cox-de Boor, K=3, uniform knots grid[j] = 0.25j - 1.75 (exact fp32) ----
        float ba[14], bc[14];
        #pragma unroll
        for (int j = 0; j < 14; ++j) {
            const float gj = 0.25f * (float)j - 1.75f;
            ba[j] = (xi.x >= gj && xi.x < gj + 0.25f) ? 1.f : 0.f;
            bc[j] = (xi.y >= gj && xi.y < gj + 0.25f) ? 1.f : 0.f;
        }
        const float ta = fmaf(xi.x, 4.0f, 7.0f);
        const float tc = fmaf(xi.y, 4.0f, 7.0f);
        #pragma unroll
        for (int p = 1; p <= 3; ++p) {
            const float invp = 1.0f / (float)p;
            #pragma unroll
            for (int j = 0; j < 14 - p; ++j) {
                const float la = (ta - (float)j) * invp;
                const float ra = ((float)(j + p + 1) - ta) * invp;
                ba[j] = la * ba[j] + ra * ba[j + 1];
                const float lc = (tc - (float)j) * invp;
                const float rc = ((float)(j + p + 1) - tc) * invp;
                bc[j] = lc * bc[j] + rc * bc[j + 1];
            }
        }
        const float sxa = xi.x / (1.0f + __expf(-xi.x));
        const float sxb = xi.y / (1.0f + __expf(-xi.y));

        // ---- spline contraction: coefs from smem stage st ----
        const char* stp = sbuf + st * STAGE_B + (size_t)warp * SEG_B + (size_t)lane * 8;
        float s0a = 0.f, s0b = 0.f, s1a = 0.f, s1b = 0.f;
        #pragma unroll
        for (int m = 0; m < COEFM; ++m) {
            const float2 c0 = *(const float2*)(stp + (size_t)m * (NW * SEG_B));
            const float2 c1 = *(const float2*)(stp + (size_t)(COEFM + m) * (NW * SEG_B));
            s0a = fmaf(c0.x, ba[m], s0a);
            s0b = fmaf(c0.y, bc[m], s0b);
            s1a = fmaf(c1.x, ba[m], s1a);
            s1b = fmaf(c1.y, bc[m], s1b);
        }
        const float2 u0 = ldcs2(up + 0 * HW2);
        const float2 u1 = ldcs2(up + 1 * HW2);
        const float2 r0 = ldcs2(rp + 0 * HW2);
        const float2 r1 = ldcs2(rp + 1 * HW2);
        y0a += u0.x * s0a + r0.x * sxa;
        y0b += u0.y * s0b + r0.y * sxb;
        y1a += u1.x * s1a + r1.x * sxa;
        y1b += u1.y * s1b + r1.y * sxb;

        up += (size_t)OUTC * HW2;
        rp += (size_t)OUTC * HW2;

        __syncwarp();              // all lanes done reading stage st before it is rewritten
    }

    float2* op = (float2*)(out + (size_t)b * OUTC * HW) + (size_t)(slice * 2) * HW2 + hw2;
    op[0 * HW2] = make_float2(y0a, y0b);
    op[1 * HW2] = make_float2(y1a, y1b);
}

extern "C" void kernel_launch(void* const* d_in, const int* in_sizes, int n_in,
                              void* d_out, int out_size)
{
    const float* x = (const float*)d_in[0];
    const float* w = (const float*)d_in[1];
    float* out = (float*)d_out;

    dim3 grid(16384 / TPB, OSPLIT);   // (128, 8) = 1024 blocks of 128 threads
    kan_kernel<<<grid, TPB>>>(x, w, out);
}

// round 9
// speedup vs baseline: 1.3308x; 1.3308x over previous
#include <cuda_runtime.h>

// ConvSepKanCell: per-pixel dynamic KAN — float2 (2 pixels/thread), 2 outputs/thread,
// software-pipelined: u/r hoisted to top of iteration, x prefetched one iter ahead.
// x: (2, 16, 128, 128) f32   w: (2, 3328, 128, 128) f32   out: (2, 16, 128, 128) f32
// Param layout along dim-1 of w (per pixel):
//   [0, 2816)      coef[i][o][m]  (16 x 16 x 11)
//   [2816, 3072)   uw[i][o]
//   [3072, 3328)   rw[i][o]
// y[o] = sum_i uw[i][o] * (sum_m coef[i][o][m]*B3_m(x_i)) + rw[i][o]*silu(x_i)

#define HW      16384
#define HW2     8192      // float2 elements per image plane
#define INC     16
#define OUTC    16
#define COEFM   11
#define SIZE_W  3328
#define I0      2816
#define I1      3072
#define OSPLIT  8         // outputs per thread = 2
#define TPB     128

__device__ __forceinline__ float2 ldcs2(const float2* p) { return __ldcs(p); }

__global__ __launch_bounds__(TPB, 7)
void kan_kernel(const float* __restrict__ x,
                const float* __restrict__ w,
                float* __restrict__ out)
{
    const int t     = blockIdx.x * TPB + threadIdx.x;   // 0..16383 (float2 slots)
    const int slice = blockIdx.y;                       // 0..7 -> outputs slice*2..+2
    const int b   = t >> 13;
    const int hw2 = t & (HW2 - 1);

    const float2* wp = (const float2*)(w + (size_t)b * SIZE_W * HW) + hw2;
    const float2* xp = (const float2*)(x + (size_t)b * INC * HW) + hw2;

    const float2* cp = wp + (size_t)(slice * 2 * COEFM) * HW2;
    const float2* up = wp + (size_t)(I0 + slice * 2) * HW2;
    const float2* rp = wp + (size_t)(I1 + slice * 2) * HW2;

    float y0a = 0.f, y0b = 0.f, y1a = 0.f, y1b = 0.f;

    float2 xi = __ldg(xp);           // x for iteration 0
    xp += HW2;

    for (int i = 0; i < INC; ++i) {
        // ---- hoisted independent loads: u/r for this iter, x for next iter ----
        const float2 u0 = ldcs2(up + 0 * HW2);
        const float2 u1 = ldcs2(up + 1 * HW2);
        const float2 r0 = ldcs2(rp + 0 * HW2);
        const float2 r1 = ldcs2(rp + 1 * HW2);
        float2 xn;
        if (i < INC - 1) { xn = __ldg(xp); xp += HW2; }

        // ---- Cox-de Boor, K=3, uniform knots grid[j] = 0.25j - 1.75 (exact fp32) ----
        float ba[14], bc[14];
        #pragma unroll
        for (int j = 0; j < 14; ++j) {
            const float gj = 0.25f * (float)j - 1.75f;
            ba[j] = (xi.x >= gj && xi.x < gj + 0.25f) ? 1.f : 0.f;
            bc[j] = (xi.y >= gj && xi.y < gj + 0.25f) ? 1.f : 0.f;
        }
        const float ta = fmaf(xi.x, 4.0f, 7.0f);
        const float tc = fmaf(xi.y, 4.0f, 7.0f);
        #pragma unroll
        for (int p = 1; p <= 3; ++p) {
            const float invp = 1.0f / (float)p;
            #pragma unroll
            for (int j = 0; j < 14 - p; ++j) {
                const float la = (ta - (float)j) * invp;
                const float ra = ((float)(j + p + 1) - ta) * invp;
                ba[j] = la * ba[j] + ra * ba[j + 1];
                const float lc = (tc - (float)j) * invp;
                const float rc = ((float)(j + p + 1) - tc) * invp;
                bc[j] = lc * bc[j] + rc * bc[j + 1];
            }
        }
        const float sxa = xi.x / (1.0f + __expf(-xi.x));
        const float sxb = xi.y / (1.0f + __expf(-xi.y));

        // ---- spline contraction for 2 outputs x 2 pixels ----
        float s0a = 0.f, s0b = 0.f, s1a = 0.f, s1b = 0.f;
        #pragma unroll
        for (int m = 0; m < COEFM; ++m) {
            const float2 c0 = ldcs2(cp + (0 * COEFM + m) * HW2);
            const float2 c1 = ldcs2(cp + (1 * COEFM + m) * HW2);
            s0a = fmaf(c0.x, ba[m], s0a);
            s0b = fmaf(c0.y, bc[m], s0b);
            s1a = fmaf(c1.x, ba[m], s1a);
            s1b = fmaf(c1.y, bc[m], s1b);
        }
        y0a += u0.x * s0a + r0.x * sxa;
        y0b += u0.y * s0b + r0.y * sxb;
        y1a += u1.x * s1a + r1.x * sxa;
        y1b += u1.y * s1b + r1.y * sxb;

        xi = xn;
        cp += (size_t)(OUTC * COEFM) * HW2;
        up += (size_t)OUTC * HW2;
        rp += (size_t)OUTC * HW2;
    }

    float2* op = (float2*)(out + (size_t)b * OUTC * HW) + (size_t)(slice * 2) * HW2 + hw2;
    op[0 * HW2] = make_float2(y0a, y0b);
    op[1 * HW2] = make_float2(y1a, y1b);
}

extern "C" void kernel_launch(void* const* d_in, const int* in_sizes, int n_in,
                              void* d_out, int out_size)
{
    const float* x = (const float*)d_in[0];
    const float* w = (const float*)d_in[1];
    float* out = (float*)d_out;

    dim3 grid(16384 / TPB, OSPLIT);   // (128, 8) = 1024 blocks of 128 threads
    kan_kernel<<<grid, TPB>>>(x, w, out);
}